// round 3
// baseline (speedup 1.0000x reference)
#include <cuda_runtime.h>

#define NA 50000
#define NM 50000
#define NI 600000
#define NG 512
#define H 64
#define MD 94
#define HOUT 128
#define ZK 158
#define ZKP 160          // padded K
#define NZ 101
#define BN_EPS 1e-5f

// ---------------- device scratch ----------------
__device__ __align__(256) float d_hx[NM * H];     // hyperedge SUM
__device__ __align__(256) float d_Tf[NZ * H];
__device__ __align__(256) float d_Tc[NZ * H];
__device__ __align__(256) float d_Mf[NM * H];
__device__ __align__(256) float d_Mc[NM * H];
__device__ __align__(256) float d_out[NA * H];    // per-atom MEAN message
__device__ float d_bnsum[H];
__device__ float d_bnsq[H];
__device__ __align__(256) float d_gsum[NG * H];
__device__ float d_gcnt[NG];
// sort machinery
__device__ int d_icnt_s[NA];
__device__ int d_icnt_h[NM];
__device__ int d_off_s[NA + 1];
__device__ int d_off_h[NM + 1];
__device__ int d_cur_s[NA];
__device__ int d_cur_h[NM];
__device__ int d_zA[NI];     // atom-type per incidence, sorted by hid
__device__ int d_hB[NI];     // motif id per incidence, sorted by src

// ---------------- fast math ----------------
__device__ __forceinline__ float ex2f(float x) { float r; asm("ex2.approx.ftz.f32 %0,%1;" : "=f"(r) : "f"(x)); return r; }
__device__ __forceinline__ float lg2f(float x) { float r; asm("lg2.approx.ftz.f32 %0,%1;" : "=f"(r) : "f"(x)); return r; }
__device__ __forceinline__ float rcpf(float x) { float r; asm("rcp.approx.ftz.f32 %0,%1;" : "=f"(r) : "f"(x)); return r; }

#define L2E 1.4426950408889634f
#define LN2 0.6931471805599453f

__device__ __forceinline__ float gatef(float a, float b) {
    float sg = rcpf(1.0f + ex2f(-a * L2E));
    float sp = lg2f(1.0f + ex2f(b * L2E)) * LN2;
    return sg * sp;
}

__device__ __forceinline__ void red_add_v4(float* p, float4 v) {
    asm volatile("red.global.add.v4.f32 [%0], {%1,%2,%3,%4};"
                 :: "l"(p), "f"(v.x), "f"(v.y), "f"(v.z), "f"(v.w) : "memory");
}
__device__ __forceinline__ void red_add_1(float* p, float v) {
    asm volatile("red.global.add.f32 [%0], %1;" :: "l"(p), "f"(v) : "memory");
}

// ---------------- kernels ----------------
__global__ void k_zero() {
    int tid = blockIdx.x * blockDim.x + threadIdx.x;
    int stride = gridDim.x * blockDim.x;
    for (int i = tid; i < NA; i += stride) d_icnt_s[i] = 0;
    for (int i = tid; i < NM; i += stride) d_icnt_h[i] = 0;
    for (int i = tid; i < NG * H; i += stride) d_gsum[i] = 0.f;
    if (tid < NG) d_gcnt[tid] = 0.f;
    if (tid < H) { d_bnsum[tid] = 0.f; d_bnsq[tid] = 0.f; }
}

__global__ __launch_bounds__(128) void k_tables(const float* __restrict__ emb,
                                                const float* __restrict__ w_f,
                                                const float* __restrict__ w_c) {
    __shared__ float e[H];
    int z = blockIdx.x;
    int tx = threadIdx.x;
    if (tx < H) e[tx] = emb[z * H + tx];
    __syncthreads();
    float acc = 0.f;
    if (tx < 64) {
#pragma unroll 8
        for (int k = 0; k < H; k++) acc = fmaf(e[k], w_f[k * H + tx], acc);
        d_Tf[z * H + tx] = acc;
    } else {
        int j = tx - 64;
#pragma unroll 8
        for (int k = 0; k < H; k++) acc = fmaf(e[k], w_c[k * H + j], acc);
        d_Tc[z * H + j] = acc;
    }
}

__global__ void k_counts(const int* __restrict__ src, const int* __restrict__ hid,
                         const int* __restrict__ batch) {
    int e = blockIdx.x * blockDim.x + threadIdx.x;
    if (e < NI) {
        atomicAdd(&d_icnt_s[src[e]], 1);
        atomicAdd(&d_icnt_h[hid[e]], 1);
    }
    if (e < NA) red_add_1(&d_gcnt[batch[e]], 1.0f);
}

__device__ void scan_one(const int* __restrict__ cnt, int* __restrict__ off,
                         int* __restrict__ cur, int n) {
    __shared__ int part[1024];
    __syncthreads();
    int t = threadIdx.x;
    int per = (n + 1023) >> 10;
    int base = t * per;
    int s = 0;
    for (int i = 0; i < per; i++) {
        int idx = base + i;
        if (idx < n) s += cnt[idx];
    }
    part[t] = s;
    __syncthreads();
    for (int d = 1; d < 1024; d <<= 1) {
        int v = (t >= d) ? part[t - d] : 0;
        __syncthreads();
        part[t] += v;
        __syncthreads();
    }
    int run = part[t] - s;   // exclusive prefix for this thread's chunk
    for (int i = 0; i < per; i++) {
        int idx = base + i;
        if (idx < n) {
            off[idx] = run;
            cur[idx] = run;
            run += cnt[idx];
        }
    }
    if (t == 1023) off[n] = part[1023];
}

__global__ __launch_bounds__(1024) void k_scan() {
    scan_one(d_icnt_h, d_off_h, d_cur_h, NM);
    scan_one(d_icnt_s, d_off_s, d_cur_s, NA);
}

__global__ void k_sort(const int* __restrict__ src, const int* __restrict__ hid,
                       const int* __restrict__ az) {
    int e = blockIdx.x * blockDim.x + threadIdx.x;
    if (e >= NI) return;
    int s = src[e];
    int h = hid[e];
    int ph = atomicAdd(&d_cur_h[h], 1);
    d_zA[ph] = __ldg(az + s);
    int ps = atomicAdd(&d_cur_s[s], 1);
    d_hB[ps] = h;
}

// phase A (segmented): hx[m] = sum over segment of emb[z]
__global__ __launch_bounds__(256) void k_hx(const float* __restrict__ emb) {
    __shared__ __align__(16) float T[NZ * H];
    for (int i = threadIdx.x; i < NZ * H; i += 256) T[i] = emb[i];
    __syncthreads();
    int m = blockIdx.x * 16 + (threadIdx.x >> 4);
    int q = (threadIdx.x & 15) << 2;
    if (m >= NM) return;
    int b = d_off_h[m], e2 = d_off_h[m + 1];
    float4 acc = make_float4(0.f, 0.f, 0.f, 0.f);
    for (int j = b; j < e2; j++) {
        int z = d_zA[j];
        float4 v = *reinterpret_cast<const float4*>(&T[z * H + q]);
        acc.x += v.x; acc.y += v.y; acc.z += v.z; acc.w += v.w;
    }
    *reinterpret_cast<float4*>(&d_hx[m * H + q]) = acc;
}

// per-motif GEMM:  [Mf|Mc] = [hx_mean | attr] @ [w_f[64:] | w_c[64:]] + bias
// 64 rows x 128 cols per block; 256 threads; thread = 8 rows x 4 cols; K padded to 160
__global__ __launch_bounds__(256) void k_gemm_motifs(const float* __restrict__ w_f,
                                                     const float* __restrict__ w_c,
                                                     const float* __restrict__ b_f,
                                                     const float* __restrict__ b_c,
                                                     const float* __restrict__ attr) {
    extern __shared__ float smbuf[];
    float* Wsm = smbuf;               // ZKP * 128
    float* Xsm = smbuf + ZKP * 128;   // 64 * ZKP
    int t = threadIdx.x;
    int tx = t & 31;
    int ry = t >> 5;

    for (int idx = t; idx < ZKP * 128; idx += 256) {
        int k = idx >> 7, j = idx & 127;
        float v = 0.f;
        if (k < ZK) v = (j < 64) ? w_f[(64 + k) * H + j] : w_c[(64 + k) * H + j - 64];
        Wsm[idx] = v;
    }
    int row0 = blockIdx.x * 64;
    for (int idx = t; idx < 64 * ZKP; idx += 256) {
        int r = idx / ZKP;
        int k = idx - r * ZKP;
        int row = row0 + r;
        float v = 0.f;
        if (row < NM && k < ZK) {
            if (k < 64) v = d_hx[row * H + k] *
                            __fdividef(1.0f, fmaxf((float)d_icnt_h[row], 1.0f));
            else        v = attr[row * MD + (k - 64)];
        }
        Xsm[idx] = v;
    }
    __syncthreads();

    float acc[8][4];
#pragma unroll
    for (int r = 0; r < 8; r++)
#pragma unroll
        for (int c = 0; c < 4; c++) acc[r][c] = 0.f;

    for (int k0 = 0; k0 < ZKP; k0 += 4) {
        float4 wv[4];
#pragma unroll
        for (int i = 0; i < 4; i++)
            wv[i] = *reinterpret_cast<const float4*>(&Wsm[(k0 + i) * 128 + tx * 4]);
#pragma unroll
        for (int r = 0; r < 8; r++) {
            float4 xv = *reinterpret_cast<const float4*>(&Xsm[(ry * 8 + r) * ZKP + k0]);
            acc[r][0] = fmaf(xv.x, wv[0].x, acc[r][0]);
            acc[r][1] = fmaf(xv.x, wv[0].y, acc[r][1]);
            acc[r][2] = fmaf(xv.x, wv[0].z, acc[r][2]);
            acc[r][3] = fmaf(xv.x, wv[0].w, acc[r][3]);
            acc[r][0] = fmaf(xv.y, wv[1].x, acc[r][0]);
            acc[r][1] = fmaf(xv.y, wv[1].y, acc[r][1]);
            acc[r][2] = fmaf(xv.y, wv[1].z, acc[r][2]);
            acc[r][3] = fmaf(xv.y, wv[1].w, acc[r][3]);
            acc[r][0] = fmaf(xv.z, wv[2].x, acc[r][0]);
            acc[r][1] = fmaf(xv.z, wv[2].y, acc[r][1]);
            acc[r][2] = fmaf(xv.z, wv[2].z, acc[r][2]);
            acc[r][3] = fmaf(xv.z, wv[2].w, acc[r][3]);
            acc[r][0] = fmaf(xv.w, wv[3].x, acc[r][0]);
            acc[r][1] = fmaf(xv.w, wv[3].y, acc[r][1]);
            acc[r][2] = fmaf(xv.w, wv[3].z, acc[r][2]);
            acc[r][3] = fmaf(xv.w, wv[3].w, acc[r][3]);
        }
    }

    int col = tx * 4;
    float4 bias;
    if (col < 64) bias = *reinterpret_cast<const float4*>(&b_f[col]);
    else          bias = *reinterpret_cast<const float4*>(&b_c[col - 64]);
#pragma unroll
    for (int r = 0; r < 8; r++) {
        int row = row0 + ry * 8 + r;
        if (row < NM) {
            float4 o;
            o.x = acc[r][0] + bias.x; o.y = acc[r][1] + bias.y;
            o.z = acc[r][2] + bias.z; o.w = acc[r][3] + bias.w;
            if (col < 64) *reinterpret_cast<float4*>(&d_Mf[row * H + col]) = o;
            else          *reinterpret_cast<float4*>(&d_Mc[row * H + col - 64]) = o;
        }
    }
}

// phase B (segmented): out[s] = mean over segment of gate(Tf[z]+Mf[m], Tc[z]+Mc[m])
// fused BN statistics
__global__ __launch_bounds__(256) void k_msg(const int* __restrict__ az) {
    __shared__ float bn1[64], bn2[64];
    int t = threadIdx.x;
    if (t < 64) { bn1[t] = 0.f; bn2[t] = 0.f; }
    __syncthreads();

    int s = blockIdx.x * 16 + (t >> 4);
    int q = (t & 15) << 2;
    if (s < NA) {
        int z = __ldg(az + s);
        float4 tf = *reinterpret_cast<const float4*>(&d_Tf[z * H + q]);
        float4 tc = *reinterpret_cast<const float4*>(&d_Tc[z * H + q]);
        int b = d_off_s[s], e2 = d_off_s[s + 1];
        float4 acc = make_float4(0.f, 0.f, 0.f, 0.f);
        int j = b;
        for (; j + 1 < e2; j += 2) {
            int m0 = d_hB[j], m1 = d_hB[j + 1];
            float4 mf0 = *reinterpret_cast<const float4*>(&d_Mf[m0 * H + q]);
            float4 mc0 = *reinterpret_cast<const float4*>(&d_Mc[m0 * H + q]);
            float4 mf1 = *reinterpret_cast<const float4*>(&d_Mf[m1 * H + q]);
            float4 mc1 = *reinterpret_cast<const float4*>(&d_Mc[m1 * H + q]);
            acc.x += gatef(tf.x + mf0.x, tc.x + mc0.x) + gatef(tf.x + mf1.x, tc.x + mc1.x);
            acc.y += gatef(tf.y + mf0.y, tc.y + mc0.y) + gatef(tf.y + mf1.y, tc.y + mc1.y);
            acc.z += gatef(tf.z + mf0.z, tc.z + mc0.z) + gatef(tf.z + mf1.z, tc.z + mc1.z);
            acc.w += gatef(tf.w + mf0.w, tc.w + mc0.w) + gatef(tf.w + mf1.w, tc.w + mc1.w);
        }
        if (j < e2) {
            int m0 = d_hB[j];
            float4 mf0 = *reinterpret_cast<const float4*>(&d_Mf[m0 * H + q]);
            float4 mc0 = *reinterpret_cast<const float4*>(&d_Mc[m0 * H + q]);
            acc.x += gatef(tf.x + mf0.x, tc.x + mc0.x);
            acc.y += gatef(tf.y + mf0.y, tc.y + mc0.y);
            acc.z += gatef(tf.z + mf0.z, tc.z + mc0.z);
            acc.w += gatef(tf.w + mf0.w, tc.w + mc0.w);
        }
        float rc = __fdividef(1.0f, fmaxf((float)(e2 - b), 1.0f));
        acc.x *= rc; acc.y *= rc; acc.z *= rc; acc.w *= rc;
        *reinterpret_cast<float4*>(&d_out[s * H + q]) = acc;
        atomicAdd(&bn1[q + 0], acc.x); atomicAdd(&bn2[q + 0], acc.x * acc.x);
        atomicAdd(&bn1[q + 1], acc.y); atomicAdd(&bn2[q + 1], acc.y * acc.y);
        atomicAdd(&bn1[q + 2], acc.z); atomicAdd(&bn2[q + 2], acc.z * acc.z);
        atomicAdd(&bn1[q + 3], acc.w); atomicAdd(&bn2[q + 3], acc.w * acc.w);
    }
    __syncthreads();
    if (t < 64) {
        red_add_1(&d_bnsum[t], bn1[t]);
        red_add_1(&d_bnsq[t], bn2[t]);
    }
}

// normalize + residual + relu + pool into graphs
__global__ void k_final(const int* __restrict__ batch, const float* __restrict__ gamma,
                        const float* __restrict__ beta, const int* __restrict__ az,
                        const float* __restrict__ emb) {
    int tid = blockIdx.x * blockDim.x + threadIdx.x;
    if (tid >= NA * 16) return;
    int i = tid >> 4;
    int q = (tid & 15) << 2;
    int z = __ldg(az + i);
    float4 o = *reinterpret_cast<const float4*>(&d_out[i * H + q]);
    float4 xv = *reinterpret_cast<const float4*>(&emb[z * H + q]);
    float ov[4] = {o.x, o.y, o.z, o.w};
    float xr[4] = {xv.x, xv.y, xv.z, xv.w};
    float res[4];
#pragma unroll
    for (int c = 0; c < 4; c++) {
        int f = q + c;
        float mu = d_bnsum[f] * (1.0f / NA);
        float var = d_bnsq[f] * (1.0f / NA) - mu * mu;
        float inv = rsqrtf(var + BN_EPS);
        float v = (ov[c] - mu) * inv * gamma[f] + beta[f] + xr[c];
        res[c] = fmaxf(v, 0.f);
    }
    float4 r; r.x = res[0]; r.y = res[1]; r.z = res[2]; r.w = res[3];
    int g = __ldg(batch + i);
    red_add_v4(&d_gsum[g * H + q], r);
}

// MLP head
__global__ __launch_bounds__(128) void k_head(const float* __restrict__ w_l1,
                                              const float* __restrict__ b_l1,
                                              const float* __restrict__ w_out,
                                              const float* __restrict__ b_out,
                                              float* __restrict__ out) {
    __shared__ float gsm[64];
    __shared__ float red[128];
    int g = blockIdx.x;
    int t = threadIdx.x;
    if (t < 64) gsm[t] = d_gsum[g * H + t] * __fdividef(1.0f, fmaxf(d_gcnt[g], 1.0f));
    __syncthreads();
    float acc = b_l1[t];
#pragma unroll
    for (int f = 0; f < 64; f++)
        acc = fmaf(gsm[f], w_l1[f * HOUT + t], acc);
    float sp = lg2f(1.0f + ex2f(acc * L2E)) * LN2;
    red[t] = sp * w_out[t];
    __syncthreads();
    if (t < 64) red[t] += red[t + 64];
    __syncthreads();
    if (t < 32) {
        float s = red[t] + red[t + 32];
#pragma unroll
        for (int off = 16; off > 0; off >>= 1)
            s += __shfl_down_sync(0xffffffff, s, off);
        if (t == 0) out[g] = s + b_out[0];
    }
}

// ---------------- launch ----------------
extern "C" void kernel_launch(void* const* d_in, const int* in_sizes, int n_in,
                              void* d_out_p, int out_size) {
    const int*   atom_z = (const int*)d_in[0];
    const float* attr   = (const float*)d_in[1];
    const int*   hei    = (const int*)d_in[2];
    const int*   batch  = (const int*)d_in[3];
    const float* emb    = (const float*)d_in[4];
    const float* w_f    = (const float*)d_in[5];
    const float* b_f    = (const float*)d_in[6];
    const float* w_c    = (const float*)d_in[7];
    const float* b_c    = (const float*)d_in[8];
    const float* gamma  = (const float*)d_in[9];
    const float* beta   = (const float*)d_in[10];
    const float* w_l1   = (const float*)d_in[11];
    const float* b_l1   = (const float*)d_in[12];
    const float* w_out  = (const float*)d_in[13];
    const float* b_out  = (const float*)d_in[14];
    float* out = (float*)d_out_p;

    const int* src = hei;
    const int* hid = hei + NI;

    const int gemm_smem = (ZKP * 128 + 64 * ZKP) * (int)sizeof(float);  // 122880 B
    cudaFuncSetAttribute(k_gemm_motifs, cudaFuncAttributeMaxDynamicSharedMemorySize, gemm_smem);

    k_zero<<<256, 256>>>();
    k_tables<<<NZ, 128>>>(emb, w_f, w_c);
    k_counts<<<(NI + 255) / 256, 256>>>(src, hid, batch);
    k_scan<<<1, 1024>>>();
    k_sort<<<(NI + 255) / 256, 256>>>(src, hid, atom_z);
    k_hx<<<(NM + 15) / 16, 256>>>(emb);
    k_gemm_motifs<<<(NM + 63) / 64, 256, gemm_smem>>>(w_f, w_c, b_f, b_c, attr);
    k_msg<<<(NA + 15) / 16, 256>>>(atom_z);
    k_final<<<(NA * 16 + 255) / 256, 256>>>(batch, gamma, beta, atom_z, emb);
    k_head<<<NG, 128>>>(w_l1, b_l1, w_out, b_out, out);
}

// round 4
// speedup vs baseline: 1.4979x; 1.4979x over previous
#include <cuda_runtime.h>

#define NA 50000
#define NM 50000
#define NI 600000
#define NG 512
#define H 64
#define MD 94
#define HOUT 128
#define ZK 158
#define ZKP 160
#define NZ 101
#define BN_EPS 1e-5f
#define SCAN_BLOCKS ((NA + 255) / 256)   // 196

// ---------------- device scratch ----------------
__device__ __align__(256) float d_hx[NM * H];
__device__ __align__(256) float d_cnt_h[NM];
__device__ __align__(256) float d_Tf[NZ * H];
__device__ __align__(256) float d_Tc[NZ * H];
__device__ __align__(256) float d_Mf[NM * H];
__device__ __align__(256) float d_Mc[NM * H];
__device__ __align__(256) float d_out[NA * H];
__device__ float d_bnsum[H];
__device__ float d_bnsq[H];
__device__ __align__(256) float d_gsum[NG * H];
__device__ float d_gcnt[NG];
// src-side sort machinery
__device__ int d_icnt_s[NA];
__device__ int d_off_s[NA + 1];
__device__ int d_cur_s[NA];
__device__ int d_bsum[SCAN_BLOCKS];
__device__ int d_boff[SCAN_BLOCKS];
__device__ int d_hB[NI];      // motif id per incidence, sorted by src

// ---------------- fast math ----------------
__device__ __forceinline__ float ex2f(float x) { float r; asm("ex2.approx.ftz.f32 %0,%1;" : "=f"(r) : "f"(x)); return r; }
__device__ __forceinline__ float lg2f(float x) { float r; asm("lg2.approx.ftz.f32 %0,%1;" : "=f"(r) : "f"(x)); return r; }
__device__ __forceinline__ float rcpf(float x) { float r; asm("rcp.approx.ftz.f32 %0,%1;" : "=f"(r) : "f"(x)); return r; }

#define L2E 1.4426950408889634f
#define LN2 0.6931471805599453f

__device__ __forceinline__ float gatef(float a, float b) {
    float sg = rcpf(1.0f + ex2f(-a * L2E));
    float sp = lg2f(1.0f + ex2f(b * L2E)) * LN2;
    return sg * sp;
}

__device__ __forceinline__ void red_add_v4(float* p, float4 v) {
    asm volatile("red.global.add.v4.f32 [%0], {%1,%2,%3,%4};"
                 :: "l"(p), "f"(v.x), "f"(v.y), "f"(v.z), "f"(v.w) : "memory");
}
__device__ __forceinline__ void red_add_1(float* p, float v) {
    asm volatile("red.global.add.f32 [%0], %1;" :: "l"(p), "f"(v) : "memory");
}

// ---------------- kernels ----------------
__global__ void k_zero() {
    int tid = blockIdx.x * blockDim.x + threadIdx.x;
    int stride = gridDim.x * blockDim.x;
    for (int i = tid; i < NM * H; i += stride) d_hx[i] = 0.f;
    for (int i = tid; i < NA; i += stride) d_icnt_s[i] = 0;
    for (int i = tid; i < NM; i += stride) d_cnt_h[i] = 0.f;
    for (int i = tid; i < NG * H; i += stride) d_gsum[i] = 0.f;
    if (tid < NG) d_gcnt[tid] = 0.f;
    if (tid < H) { d_bnsum[tid] = 0.f; d_bnsq[tid] = 0.f; }
    if (tid == 0) d_off_s[NA] = NI;   // total incidences is a constant
}

__global__ __launch_bounds__(128) void k_tables(const float* __restrict__ emb,
                                                const float* __restrict__ w_f,
                                                const float* __restrict__ w_c) {
    __shared__ float e[H];
    int z = blockIdx.x;
    int tx = threadIdx.x;
    if (tx < H) e[tx] = emb[z * H + tx];
    __syncthreads();
    float acc = 0.f;
    if (tx < 64) {
#pragma unroll 8
        for (int k = 0; k < H; k++) acc = fmaf(e[k], w_f[k * H + tx], acc);
        d_Tf[z * H + tx] = acc;
    } else {
        int j = tx - 64;
#pragma unroll 8
        for (int k = 0; k < H; k++) acc = fmaf(e[k], w_c[k * H + j], acc);
        d_Tc[z * H + j] = acc;
    }
}

__global__ void k_counts(const int* __restrict__ src, const int* __restrict__ batch) {
    int e = blockIdx.x * blockDim.x + threadIdx.x;
    if (e < NI) atomicAdd(&d_icnt_s[src[e]], 1);
    if (e < NA) red_add_1(&d_gcnt[batch[e]], 1.0f);
}

// ---- 3-pass exclusive scan over d_icnt_s[NA] ----
__global__ __launch_bounds__(256) void k_scan1() {
    __shared__ int sh[256];
    int t = threadIdx.x;
    int i = blockIdx.x * 256 + t;
    int v = (i < NA) ? d_icnt_s[i] : 0;
    sh[t] = v;
    __syncthreads();
#pragma unroll
    for (int d = 1; d < 256; d <<= 1) {
        int u = (t >= d) ? sh[t - d] : 0;
        __syncthreads();
        sh[t] += u;
        __syncthreads();
    }
    if (i < NA) d_off_s[i] = sh[t] - v;      // local exclusive
    if (t == 255) d_bsum[blockIdx.x] = sh[255];
}

__global__ __launch_bounds__(256) void k_scan2() {
    __shared__ int sh[256];
    int t = threadIdx.x;
    int v = (t < SCAN_BLOCKS) ? d_bsum[t] : 0;
    sh[t] = v;
    __syncthreads();
#pragma unroll
    for (int d = 1; d < 256; d <<= 1) {
        int u = (t >= d) ? sh[t - d] : 0;
        __syncthreads();
        sh[t] += u;
        __syncthreads();
    }
    if (t < SCAN_BLOCKS) d_boff[t] = sh[t] - v;   // exclusive
}

__global__ __launch_bounds__(256) void k_scan3() {
    int i = blockIdx.x * 256 + threadIdx.x;
    if (i < NA) {
        int o = d_off_s[i] + d_boff[blockIdx.x];
        d_off_s[i] = o;
        d_cur_s[i] = o;
    }
}

__global__ void k_sort(const int* __restrict__ src, const int* __restrict__ hid) {
    int e = blockIdx.x * blockDim.x + threadIdx.x;
    if (e >= NI) return;
    int s = src[e];
    int ps = atomicAdd(&d_cur_s[s], 1);
    d_hB[ps] = hid[e];
}

// phase A: red.v4 scatter emb[z[src]] -> hx[hid], fused cnt_h
__global__ __launch_bounds__(256) void k_scatter(const int* __restrict__ src,
                                                 const int* __restrict__ hid,
                                                 const int* __restrict__ az,
                                                 const float* __restrict__ emb) {
    __shared__ __align__(16) float T[NZ * H];
    for (int i = threadIdx.x; i < NZ * H; i += 256) T[i] = emb[i];
    __syncthreads();
    int stride = gridDim.x * 256;
    for (int idx = blockIdx.x * 256 + threadIdx.x; idx < NI * 16; idx += stride) {
        int e = idx >> 4;
        int q = (idx & 15) << 2;
        int s = __ldg(src + e);
        int m = __ldg(hid + e);
        int z = __ldg(az + s);
        float4 v = *reinterpret_cast<const float4*>(&T[z * H + q]);
        red_add_v4(d_hx + m * H + q, v);
        if ((idx & 15) == 0) red_add_1(&d_cnt_h[m], 1.0f);
    }
}

// per-motif GEMM:  [Mf|Mc] = [hx_mean | attr] @ [w_f[64:] | w_c[64:]] + bias
__global__ __launch_bounds__(256) void k_gemm_motifs(const float* __restrict__ w_f,
                                                     const float* __restrict__ w_c,
                                                     const float* __restrict__ b_f,
                                                     const float* __restrict__ b_c,
                                                     const float* __restrict__ attr) {
    extern __shared__ float smbuf[];
    float* Wsm = smbuf;               // ZKP * 128
    float* Xsm = smbuf + ZKP * 128;   // 64 * ZKP
    int t = threadIdx.x;
    int tx = t & 31;
    int ry = t >> 5;

    for (int idx = t; idx < ZKP * 128; idx += 256) {
        int k = idx >> 7, j = idx & 127;
        float v = 0.f;
        if (k < ZK) v = (j < 64) ? w_f[(64 + k) * H + j] : w_c[(64 + k) * H + j - 64];
        Wsm[idx] = v;
    }
    int row0 = blockIdx.x * 64;
    for (int idx = t; idx < 64 * ZKP; idx += 256) {
        int r = idx / ZKP;
        int k = idx - r * ZKP;
        int row = row0 + r;
        float v = 0.f;
        if (row < NM && k < ZK) {
            if (k < 64) v = d_hx[row * H + k] *
                            __fdividef(1.0f, fmaxf(d_cnt_h[row], 1.0f));
            else        v = attr[row * MD + (k - 64)];
        }
        Xsm[idx] = v;
    }
    __syncthreads();

    float acc[8][4];
#pragma unroll
    for (int r = 0; r < 8; r++)
#pragma unroll
        for (int c = 0; c < 4; c++) acc[r][c] = 0.f;

    for (int k0 = 0; k0 < ZKP; k0 += 4) {
        float4 wv[4];
#pragma unroll
        for (int i = 0; i < 4; i++)
            wv[i] = *reinterpret_cast<const float4*>(&Wsm[(k0 + i) * 128 + tx * 4]);
#pragma unroll
        for (int r = 0; r < 8; r++) {
            float4 xv = *reinterpret_cast<const float4*>(&Xsm[(ry * 8 + r) * ZKP + k0]);
            acc[r][0] = fmaf(xv.x, wv[0].x, acc[r][0]);
            acc[r][1] = fmaf(xv.x, wv[0].y, acc[r][1]);
            acc[r][2] = fmaf(xv.x, wv[0].z, acc[r][2]);
            acc[r][3] = fmaf(xv.x, wv[0].w, acc[r][3]);
            acc[r][0] = fmaf(xv.y, wv[1].x, acc[r][0]);
            acc[r][1] = fmaf(xv.y, wv[1].y, acc[r][1]);
            acc[r][2] = fmaf(xv.y, wv[1].z, acc[r][2]);
            acc[r][3] = fmaf(xv.y, wv[1].w, acc[r][3]);
            acc[r][0] = fmaf(xv.z, wv[2].x, acc[r][0]);
            acc[r][1] = fmaf(xv.z, wv[2].y, acc[r][1]);
            acc[r][2] = fmaf(xv.z, wv[2].z, acc[r][2]);
            acc[r][3] = fmaf(xv.z, wv[2].w, acc[r][3]);
            acc[r][0] = fmaf(xv.w, wv[3].x, acc[r][0]);
            acc[r][1] = fmaf(xv.w, wv[3].y, acc[r][1]);
            acc[r][2] = fmaf(xv.w, wv[3].z, acc[r][2]);
            acc[r][3] = fmaf(xv.w, wv[3].w, acc[r][3]);
        }
    }

    int col = tx * 4;
    float4 bias;
    if (col < 64) bias = *reinterpret_cast<const float4*>(&b_f[col]);
    else          bias = *reinterpret_cast<const float4*>(&b_c[col - 64]);
#pragma unroll
    for (int r = 0; r < 8; r++) {
        int row = row0 + ry * 8 + r;
        if (row < NM) {
            float4 o;
            o.x = acc[r][0] + bias.x; o.y = acc[r][1] + bias.y;
            o.z = acc[r][2] + bias.z; o.w = acc[r][3] + bias.w;
            if (col < 64) *reinterpret_cast<float4*>(&d_Mf[row * H + col]) = o;
            else          *reinterpret_cast<float4*>(&d_Mc[row * H + col - 64]) = o;
        }
    }
}

// phase B (segmented): out[s] = mean of gate(Tf[z]+Mf[m], Tc[z]+Mc[m]); BN fused
__global__ __launch_bounds__(256) void k_msg(const int* __restrict__ az) {
    __shared__ float bn1[64], bn2[64];
    int t = threadIdx.x;
    if (t < 64) { bn1[t] = 0.f; bn2[t] = 0.f; }
    __syncthreads();

    int s = blockIdx.x * 16 + (t >> 4);
    int q = (t & 15) << 2;
    if (s < NA) {
        int z = __ldg(az + s);
        float4 tf = *reinterpret_cast<const float4*>(&d_Tf[z * H + q]);
        float4 tc = *reinterpret_cast<const float4*>(&d_Tc[z * H + q]);
        int b = d_off_s[s], e2 = d_off_s[s + 1];
        float4 acc = make_float4(0.f, 0.f, 0.f, 0.f);
        int j = b;
        for (; j + 1 < e2; j += 2) {
            int m0 = d_hB[j], m1 = d_hB[j + 1];
            float4 mf0 = *reinterpret_cast<const float4*>(&d_Mf[m0 * H + q]);
            float4 mc0 = *reinterpret_cast<const float4*>(&d_Mc[m0 * H + q]);
            float4 mf1 = *reinterpret_cast<const float4*>(&d_Mf[m1 * H + q]);
            float4 mc1 = *reinterpret_cast<const float4*>(&d_Mc[m1 * H + q]);
            acc.x += gatef(tf.x + mf0.x, tc.x + mc0.x) + gatef(tf.x + mf1.x, tc.x + mc1.x);
            acc.y += gatef(tf.y + mf0.y, tc.y + mc0.y) + gatef(tf.y + mf1.y, tc.y + mc1.y);
            acc.z += gatef(tf.z + mf0.z, tc.z + mc0.z) + gatef(tf.z + mf1.z, tc.z + mc1.z);
            acc.w += gatef(tf.w + mf0.w, tc.w + mc0.w) + gatef(tf.w + mf1.w, tc.w + mc1.w);
        }
        if (j < e2) {
            int m0 = d_hB[j];
            float4 mf0 = *reinterpret_cast<const float4*>(&d_Mf[m0 * H + q]);
            float4 mc0 = *reinterpret_cast<const float4*>(&d_Mc[m0 * H + q]);
            acc.x += gatef(tf.x + mf0.x, tc.x + mc0.x);
            acc.y += gatef(tf.y + mf0.y, tc.y + mc0.y);
            acc.z += gatef(tf.z + mf0.z, tc.z + mc0.z);
            acc.w += gatef(tf.w + mf0.w, tc.w + mc0.w);
        }
        float rc = __fdividef(1.0f, fmaxf((float)(e2 - b), 1.0f));
        acc.x *= rc; acc.y *= rc; acc.z *= rc; acc.w *= rc;
        *reinterpret_cast<float4*>(&d_out[s * H + q]) = acc;
        atomicAdd(&bn1[q + 0], acc.x); atomicAdd(&bn2[q + 0], acc.x * acc.x);
        atomicAdd(&bn1[q + 1], acc.y); atomicAdd(&bn2[q + 1], acc.y * acc.y);
        atomicAdd(&bn1[q + 2], acc.z); atomicAdd(&bn2[q + 2], acc.z * acc.z);
        atomicAdd(&bn1[q + 3], acc.w); atomicAdd(&bn2[q + 3], acc.w * acc.w);
    }
    __syncthreads();
    if (t < 64) {
        red_add_1(&d_bnsum[t], bn1[t]);
        red_add_1(&d_bnsq[t], bn2[t]);
    }
}

// normalize + residual + relu + pool into graphs
__global__ void k_final(const int* __restrict__ batch, const float* __restrict__ gamma,
                        const float* __restrict__ beta, const int* __restrict__ az,
                        const float* __restrict__ emb) {
    int tid = blockIdx.x * blockDim.x + threadIdx.x;
    if (tid >= NA * 16) return;
    int i = tid >> 4;
    int q = (tid & 15) << 2;
    int z = __ldg(az + i);
    float4 o = *reinterpret_cast<const float4*>(&d_out[i * H + q]);
    float4 xv = *reinterpret_cast<const float4*>(&emb[z * H + q]);
    float ov[4] = {o.x, o.y, o.z, o.w};
    float xr[4] = {xv.x, xv.y, xv.z, xv.w};
    float res[4];
#pragma unroll
    for (int c = 0; c < 4; c++) {
        int f = q + c;
        float mu = d_bnsum[f] * (1.0f / NA);
        float var = d_bnsq[f] * (1.0f / NA) - mu * mu;
        float inv = rsqrtf(var + BN_EPS);
        float v = (ov[c] - mu) * inv * gamma[f] + beta[f] + xr[c];
        res[c] = fmaxf(v, 0.f);
    }
    float4 r; r.x = res[0]; r.y = res[1]; r.z = res[2]; r.w = res[3];
    int g = __ldg(batch + i);
    red_add_v4(&d_gsum[g * H + q], r);
}

// MLP head
__global__ __launch_bounds__(128) void k_head(const float* __restrict__ w_l1,
                                              const float* __restrict__ b_l1,
                                              const float* __restrict__ w_out,
                                              const float* __restrict__ b_out,
                                              float* __restrict__ out) {
    __shared__ float gsm[64];
    __shared__ float red[128];
    int g = blockIdx.x;
    int t = threadIdx.x;
    if (t < 64) gsm[t] = d_gsum[g * H + t] * __fdividef(1.0f, fmaxf(d_gcnt[g], 1.0f));
    __syncthreads();
    float acc = b_l1[t];
#pragma unroll
    for (int f = 0; f < 64; f++)
        acc = fmaf(gsm[f], w_l1[f * HOUT + t], acc);
    float sp = lg2f(1.0f + ex2f(acc * L2E)) * LN2;
    red[t] = sp * w_out[t];
    __syncthreads();
    if (t < 64) red[t] += red[t + 64];
    __syncthreads();
    if (t < 32) {
        float s = red[t] + red[t + 32];
#pragma unroll
        for (int off = 16; off > 0; off >>= 1)
            s += __shfl_down_sync(0xffffffff, s, off);
        if (t == 0) out[g] = s + b_out[0];
    }
}

// ---------------- launch ----------------
extern "C" void kernel_launch(void* const* d_in, const int* in_sizes, int n_in,
                              void* d_out_p, int out_size) {
    const int*   atom_z = (const int*)d_in[0];
    const float* attr   = (const float*)d_in[1];
    const int*   hei    = (const int*)d_in[2];
    const int*   batch  = (const int*)d_in[3];
    const float* emb    = (const float*)d_in[4];
    const float* w_f    = (const float*)d_in[5];
    const float* b_f    = (const float*)d_in[6];
    const float* w_c    = (const float*)d_in[7];
    const float* b_c    = (const float*)d_in[8];
    const float* gamma  = (const float*)d_in[9];
    const float* beta   = (const float*)d_in[10];
    const float* w_l1   = (const float*)d_in[11];
    const float* b_l1   = (const float*)d_in[12];
    const float* w_out  = (const float*)d_in[13];
    const float* b_out  = (const float*)d_in[14];
    float* out = (float*)d_out_p;

    const int* src = hei;
    const int* hid = hei + NI;

    const int gemm_smem = (ZKP * 128 + 64 * ZKP) * (int)sizeof(float);  // 122880 B
    cudaFuncSetAttribute(k_gemm_motifs, cudaFuncAttributeMaxDynamicSharedMemorySize, gemm_smem);

    k_zero<<<512, 256>>>();
    k_tables<<<NZ, 128>>>(emb, w_f, w_c);
    k_counts<<<(NI + 255) / 256, 256>>>(src, batch);
    k_scan1<<<SCAN_BLOCKS, 256>>>();
    k_scan2<<<1, 256>>>();
    k_scan3<<<SCAN_BLOCKS, 256>>>();
    k_sort<<<(NI + 255) / 256, 256>>>(src, hid);
    k_scatter<<<1184, 256>>>(src, hid, atom_z, emb);
    k_gemm_motifs<<<(NM + 63) / 64, 256, gemm_smem>>>(w_f, w_c, b_f, b_c, attr);
    k_msg<<<(NA + 15) / 16, 256>>>(atom_z);
    k_final<<<(NA * 16 + 255) / 256, 256>>>(batch, gamma, beta, atom_z, emb);
    k_head<<<NG, 128>>>(w_l1, b_l1, w_out, b_out, out);
}

// round 5
// speedup vs baseline: 1.5509x; 1.0354x over previous
#include <cuda_runtime.h>

#define NA 50000
#define NM 50000
#define NI 600000
#define NG 512
#define H 64
#define MD 94
#define HOUT 128
#define ZK 158
#define ZKP 160
#define NZ 101
#define BN_EPS 1e-5f
#define SCAN_BLOCKS 196   // ceil(50000/256)
#define NGRP (NI / 16)    // 37500

// ---------------- device scratch ----------------
__device__ __align__(256) float d_hx[NM * H];
__device__ __align__(256) float d_Tf[NZ * H];
__device__ __align__(256) float d_Tc[NZ * H];
__device__ __align__(256) float d_Mf[NM * H];
__device__ __align__(256) float d_Mc[NM * H];
__device__ __align__(256) float d_osum[NA * H];
__device__ float d_bnsum[H];
__device__ float d_bnsq[H];
__device__ __align__(256) float d_gsum[NG * H];
__device__ float d_gcnt[NG];
// sort machinery (both sides)
__device__ int d_icnt_s[NA];
__device__ int d_icnt_h[NM];
__device__ int d_off_s[NA + 1];
__device__ int d_off_h[NM + 1];
__device__ int d_cur_s[NA];
__device__ int d_cur_h[NM];
__device__ int d_bsum[2][SCAN_BLOCKS];
__device__ int d_boff[2][SCAN_BLOCKS];
__device__ float d_rcs[NA];       // 1/max(cnt_s,1)
__device__ float d_rch[NM];       // 1/max(cnt_h,1)
__device__ int   d_zA[NI];        // atom TYPE per incidence, sorted by hid
__device__ uint2 d_hsB[NI];       // {motif, atom} per incidence, sorted by src

// ---------------- fast math ----------------
__device__ __forceinline__ float ex2f(float x) { float r; asm("ex2.approx.ftz.f32 %0,%1;" : "=f"(r) : "f"(x)); return r; }
__device__ __forceinline__ float lg2f(float x) { float r; asm("lg2.approx.ftz.f32 %0,%1;" : "=f"(r) : "f"(x)); return r; }
__device__ __forceinline__ float rcpf(float x) { float r; asm("rcp.approx.ftz.f32 %0,%1;" : "=f"(r) : "f"(x)); return r; }

#define L2E 1.4426950408889634f
#define LN2 0.6931471805599453f

__device__ __forceinline__ float gatef(float a, float b) {
    float sg = rcpf(1.0f + ex2f(-a * L2E));
    float sp = lg2f(1.0f + ex2f(b * L2E)) * LN2;
    return sg * sp;
}

__device__ __forceinline__ void red_add_v4(float* p, float4 v) {
    asm volatile("red.global.add.v4.f32 [%0], {%1,%2,%3,%4};"
                 :: "l"(p), "f"(v.x), "f"(v.y), "f"(v.z), "f"(v.w) : "memory");
}
__device__ __forceinline__ void red_add_1(float* p, float v) {
    asm volatile("red.global.add.f32 [%0], %1;" :: "l"(p), "f"(v) : "memory");
}

// ---------------- kernels ----------------
__global__ void k_zero() {
    int tid = blockIdx.x * blockDim.x + threadIdx.x;
    int stride = gridDim.x * blockDim.x;
    for (int i = tid; i < NA * H; i += stride) d_osum[i] = 0.f;
    for (int i = tid; i < NA; i += stride) d_icnt_s[i] = 0;
    for (int i = tid; i < NM; i += stride) d_icnt_h[i] = 0;
    for (int i = tid; i < NG * H; i += stride) d_gsum[i] = 0.f;
    if (tid < NG) d_gcnt[tid] = 0.f;
    if (tid < H) { d_bnsum[tid] = 0.f; d_bnsq[tid] = 0.f; }
    if (tid == 0) { d_off_s[NA] = NI; d_off_h[NM] = NI; }
}

__global__ __launch_bounds__(128) void k_tables(const float* __restrict__ emb,
                                                const float* __restrict__ w_f,
                                                const float* __restrict__ w_c) {
    __shared__ float e[H];
    int z = blockIdx.x;
    int tx = threadIdx.x;
    if (tx < H) e[tx] = emb[z * H + tx];
    __syncthreads();
    float acc = 0.f;
    if (tx < 64) {
#pragma unroll 8
        for (int k = 0; k < H; k++) acc = fmaf(e[k], w_f[k * H + tx], acc);
        d_Tf[z * H + tx] = acc;
    } else {
        int j = tx - 64;
#pragma unroll 8
        for (int k = 0; k < H; k++) acc = fmaf(e[k], w_c[k * H + j], acc);
        d_Tc[z * H + j] = acc;
    }
}

__global__ void k_counts(const int* __restrict__ src, const int* __restrict__ hid,
                         const int* __restrict__ batch) {
    int e = blockIdx.x * blockDim.x + threadIdx.x;
    if (e < NI) {
        atomicAdd(&d_icnt_s[src[e]], 1);
        atomicAdd(&d_icnt_h[hid[e]], 1);
    }
    if (e < NA) red_add_1(&d_gcnt[batch[e]], 1.0f);
}

// ---- exclusive scan over both count arrays (blockIdx.y selects side) ----
__global__ __launch_bounds__(256) void k_scan1() {
    __shared__ int sh[256];
    int side = blockIdx.y;
    const int* cnt = side ? d_icnt_h : d_icnt_s;
    int* off = side ? d_off_h : d_off_s;
    int t = threadIdx.x;
    int i = blockIdx.x * 256 + t;
    int v = (i < NA) ? cnt[i] : 0;
    sh[t] = v;
    __syncthreads();
#pragma unroll
    for (int d = 1; d < 256; d <<= 1) {
        int u = (t >= d) ? sh[t - d] : 0;
        __syncthreads();
        sh[t] += u;
        __syncthreads();
    }
    if (i < NA) off[i] = sh[t] - v;
    if (t == 255) d_bsum[side][blockIdx.x] = sh[255];
}

__global__ __launch_bounds__(256) void k_scan2() {
    __shared__ int sh[256];
    int side = blockIdx.x;
    int t = threadIdx.x;
    int v = (t < SCAN_BLOCKS) ? d_bsum[side][t] : 0;
    sh[t] = v;
    __syncthreads();
#pragma unroll
    for (int d = 1; d < 256; d <<= 1) {
        int u = (t >= d) ? sh[t - d] : 0;
        __syncthreads();
        sh[t] += u;
        __syncthreads();
    }
    if (t < SCAN_BLOCKS) d_boff[side][t] = sh[t] - v;
}

__global__ __launch_bounds__(256) void k_scan3() {
    int side = blockIdx.y;
    int i = blockIdx.x * 256 + threadIdx.x;
    if (i >= NA) return;
    if (side == 0) {
        int o = d_off_s[i] + d_boff[0][blockIdx.x];
        d_off_s[i] = o;
        d_cur_s[i] = o;
        d_rcs[i] = __fdividef(1.0f, fmaxf((float)d_icnt_s[i], 1.0f));
    } else {
        int o = d_off_h[i] + d_boff[1][blockIdx.x];
        d_off_h[i] = o;
        d_cur_h[i] = o;
        d_rch[i] = __fdividef(1.0f, fmaxf((float)d_icnt_h[i], 1.0f));
    }
}

// permute into both sorted orders in one pass
__global__ void k_sort(const int* __restrict__ src, const int* __restrict__ hid,
                       const int* __restrict__ az) {
    int e = blockIdx.x * blockDim.x + threadIdx.x;
    if (e >= NI) return;
    int s = src[e];
    int h = hid[e];
    int z = __ldg(az + s);
    int ph = atomicAdd(&d_cur_h[h], 1);
    d_zA[ph] = z;
    int ps = atomicAdd(&d_cur_s[s], 1);
    d_hsB[ps] = make_uint2((unsigned)h, (unsigned)s);
}

// phase A (segmented, atomic-free): hx[m] = sum over segment of emb[z]
__global__ __launch_bounds__(256) void k_hx(const float* __restrict__ emb) {
    int m = blockIdx.x * 16 + (threadIdx.x >> 4);
    if (m >= NM) return;
    int q = (threadIdx.x & 15) << 2;
    int b = d_off_h[m], e = d_off_h[m + 1];
    float4 acc = make_float4(0.f, 0.f, 0.f, 0.f);
    int j = b;
    for (; j + 3 < e; j += 4) {
        int z0 = __ldg(d_zA + j), z1 = __ldg(d_zA + j + 1);
        int z2 = __ldg(d_zA + j + 2), z3 = __ldg(d_zA + j + 3);
        float4 v0 = __ldg((const float4*)(emb + z0 * H + q));
        float4 v1 = __ldg((const float4*)(emb + z1 * H + q));
        float4 v2 = __ldg((const float4*)(emb + z2 * H + q));
        float4 v3 = __ldg((const float4*)(emb + z3 * H + q));
        acc.x += (v0.x + v1.x) + (v2.x + v3.x);
        acc.y += (v0.y + v1.y) + (v2.y + v3.y);
        acc.z += (v0.z + v1.z) + (v2.z + v3.z);
        acc.w += (v0.w + v1.w) + (v2.w + v3.w);
    }
    for (; j < e; j++) {
        int z = __ldg(d_zA + j);
        float4 v = __ldg((const float4*)(emb + z * H + q));
        acc.x += v.x; acc.y += v.y; acc.z += v.z; acc.w += v.w;
    }
    *reinterpret_cast<float4*>(&d_hx[m * H + q]) = acc;
}

// per-motif GEMM:  [Mf|Mc] = [hx_mean | attr] @ [w_f[64:] | w_c[64:]] + bias
__global__ __launch_bounds__(256) void k_gemm_motifs(const float* __restrict__ w_f,
                                                     const float* __restrict__ w_c,
                                                     const float* __restrict__ b_f,
                                                     const float* __restrict__ b_c,
                                                     const float* __restrict__ attr) {
    extern __shared__ float smbuf[];
    float* Wsm = smbuf;               // ZKP * 128
    float* Xsm = smbuf + ZKP * 128;   // 64 * ZKP
    int t = threadIdx.x;
    int tx = t & 31;
    int ry = t >> 5;

    for (int idx = t; idx < ZKP * 128; idx += 256) {
        int k = idx >> 7, j = idx & 127;
        float v = 0.f;
        if (k < ZK) v = (j < 64) ? w_f[(64 + k) * H + j] : w_c[(64 + k) * H + j - 64];
        Wsm[idx] = v;
    }
    int row0 = blockIdx.x * 64;
    for (int idx = t; idx < 64 * ZKP; idx += 256) {
        int r = idx / ZKP;
        int k = idx - r * ZKP;
        int row = row0 + r;
        float v = 0.f;
        if (row < NM && k < ZK) {
            if (k < 64) v = d_hx[row * H + k] * d_rch[row];
            else        v = attr[row * MD + (k - 64)];
        }
        Xsm[idx] = v;
    }
    __syncthreads();

    float acc[8][4];
#pragma unroll
    for (int r = 0; r < 8; r++)
#pragma unroll
        for (int c = 0; c < 4; c++) acc[r][c] = 0.f;

    for (int k0 = 0; k0 < ZKP; k0 += 4) {
        float4 wv[4];
#pragma unroll
        for (int i = 0; i < 4; i++)
            wv[i] = *reinterpret_cast<const float4*>(&Wsm[(k0 + i) * 128 + tx * 4]);
#pragma unroll
        for (int r = 0; r < 8; r++) {
            float4 xv = *reinterpret_cast<const float4*>(&Xsm[(ry * 8 + r) * ZKP + k0]);
            acc[r][0] = fmaf(xv.x, wv[0].x, acc[r][0]);
            acc[r][1] = fmaf(xv.x, wv[0].y, acc[r][1]);
            acc[r][2] = fmaf(xv.x, wv[0].z, acc[r][2]);
            acc[r][3] = fmaf(xv.x, wv[0].w, acc[r][3]);
            acc[r][0] = fmaf(xv.y, wv[1].x, acc[r][0]);
            acc[r][1] = fmaf(xv.y, wv[1].y, acc[r][1]);
            acc[r][2] = fmaf(xv.y, wv[1].z, acc[r][2]);
            acc[r][3] = fmaf(xv.y, wv[1].w, acc[r][3]);
            acc[r][0] = fmaf(xv.z, wv[2].x, acc[r][0]);
            acc[r][1] = fmaf(xv.z, wv[2].y, acc[r][1]);
            acc[r][2] = fmaf(xv.z, wv[2].z, acc[r][2]);
            acc[r][3] = fmaf(xv.z, wv[2].w, acc[r][3]);
            acc[r][0] = fmaf(xv.w, wv[3].x, acc[r][0]);
            acc[r][1] = fmaf(xv.w, wv[3].y, acc[r][1]);
            acc[r][2] = fmaf(xv.w, wv[3].z, acc[r][2]);
            acc[r][3] = fmaf(xv.w, wv[3].w, acc[r][3]);
        }
    }

    int col = tx * 4;
    float4 bias;
    if (col < 64) bias = *reinterpret_cast<const float4*>(&b_f[col]);
    else          bias = *reinterpret_cast<const float4*>(&b_c[col - 64]);
#pragma unroll
    for (int r = 0; r < 8; r++) {
        int row = row0 + ry * 8 + r;
        if (row < NM) {
            float4 o;
            o.x = acc[r][0] + bias.x; o.y = acc[r][1] + bias.y;
            o.z = acc[r][2] + bias.z; o.w = acc[r][3] + bias.w;
            if (col < 64) *reinterpret_cast<float4*>(&d_Mf[row * H + col]) = o;
            else          *reinterpret_cast<float4*>(&d_Mc[row * H + col - 64]) = o;
        }
    }
}

// phase B: src-sorted chunks of 16 incidences per 16-thread group;
// register run-accumulation, red.v4 flush only on atom change.
__global__ __launch_bounds__(256) void k_msg(const int* __restrict__ az) {
    int t = threadIdx.x;
    int grp = blockIdx.x * 16 + (t >> 4);
    if (grp >= NGRP) return;
    int q = (t & 15) << 2;
    int B = grp * 16;

    int cur = -1;
    float4 acc = make_float4(0.f, 0.f, 0.f, 0.f);
    float4 tf = acc, tc = acc;

#pragma unroll
    for (int i0 = 0; i0 < 16; i0 += 4) {
        uint2 hs[4];
#pragma unroll
        for (int j = 0; j < 4; j++) hs[j] = __ldg(&d_hsB[B + i0 + j]);
        float4 mf[4], mc[4];
#pragma unroll
        for (int j = 0; j < 4; j++) {
            int m = (int)hs[j].x;
            mf[j] = __ldg((const float4*)(d_Mf + m * H + q));
            mc[j] = __ldg((const float4*)(d_Mc + m * H + q));
        }
#pragma unroll
        for (int j = 0; j < 4; j++) {
            int s = (int)hs[j].y;
            if (s != cur) {
                if (cur >= 0) red_add_v4(&d_osum[cur * H + q], acc);
                cur = s;
                acc = make_float4(0.f, 0.f, 0.f, 0.f);
                int z = __ldg(az + s);
                tf = __ldg((const float4*)(d_Tf + z * H + q));
                tc = __ldg((const float4*)(d_Tc + z * H + q));
            }
            acc.x += gatef(tf.x + mf[j].x, tc.x + mc[j].x);
            acc.y += gatef(tf.y + mf[j].y, tc.y + mc[j].y);
            acc.z += gatef(tf.z + mf[j].z, tc.z + mc[j].z);
            acc.w += gatef(tf.w + mf[j].w, tc.w + mc[j].w);
        }
    }
    red_add_v4(&d_osum[cur * H + q], acc);
}

// BN statistics over out = osum * rcs
__global__ __launch_bounds__(256) void k_bnstats() {
    __shared__ float b1[64], b2[64];
    int t = threadIdx.x;
    if (t < 64) { b1[t] = 0.f; b2[t] = 0.f; }
    __syncthreads();
    int start = blockIdx.x * 256 + t;
    int q = (start & 15) << 2;      // stride 65536 preserves low 4 bits
    float l1[4] = {0.f, 0.f, 0.f, 0.f};
    float l2[4] = {0.f, 0.f, 0.f, 0.f};
    for (int idx = start; idx < NA * 16; idx += 65536) {
        int i = idx >> 4;
        float rc = d_rcs[i];
        float4 o = *reinterpret_cast<const float4*>(&d_osum[i * H + q]);
        o.x *= rc; o.y *= rc; o.z *= rc; o.w *= rc;
        l1[0] += o.x; l2[0] += o.x * o.x;
        l1[1] += o.y; l2[1] += o.y * o.y;
        l1[2] += o.z; l2[2] += o.z * o.z;
        l1[3] += o.w; l2[3] += o.w * o.w;
    }
#pragma unroll
    for (int c = 0; c < 4; c++) {
        atomicAdd(&b1[q + c], l1[c]);
        atomicAdd(&b2[q + c], l2[c]);
    }
    __syncthreads();
    if (t < 64) {
        red_add_1(&d_bnsum[t], b1[t]);
        red_add_1(&d_bnsq[t], b2[t]);
    }
}

// normalize + residual + relu + pool
__global__ void k_final(const int* __restrict__ batch, const float* __restrict__ gamma,
                        const float* __restrict__ beta, const int* __restrict__ az,
                        const float* __restrict__ emb) {
    int tid = blockIdx.x * blockDim.x + threadIdx.x;
    if (tid >= NA * 16) return;
    int i = tid >> 4;
    int q = (tid & 15) << 2;
    int z = __ldg(az + i);
    float rc = d_rcs[i];
    float4 o = *reinterpret_cast<const float4*>(&d_osum[i * H + q]);
    float4 xv = __ldg((const float4*)(emb + z * H + q));
    float ov[4] = {o.x * rc, o.y * rc, o.z * rc, o.w * rc};
    float xr[4] = {xv.x, xv.y, xv.z, xv.w};
    float res[4];
#pragma unroll
    for (int c = 0; c < 4; c++) {
        int f = q + c;
        float mu = d_bnsum[f] * (1.0f / NA);
        float var = d_bnsq[f] * (1.0f / NA) - mu * mu;
        float inv = rsqrtf(var + BN_EPS);
        float v = (ov[c] - mu) * inv * gamma[f] + beta[f] + xr[c];
        res[c] = fmaxf(v, 0.f);
    }
    float4 r; r.x = res[0]; r.y = res[1]; r.z = res[2]; r.w = res[3];
    int g = __ldg(batch + i);
    red_add_v4(&d_gsum[g * H + q], r);
}

// MLP head
__global__ __launch_bounds__(128) void k_head(const float* __restrict__ w_l1,
                                              const float* __restrict__ b_l1,
                                              const float* __restrict__ w_out,
                                              const float* __restrict__ b_out,
                                              float* __restrict__ out) {
    __shared__ float gsm[64];
    __shared__ float red[128];
    int g = blockIdx.x;
    int t = threadIdx.x;
    if (t < 64) gsm[t] = d_gsum[g * H + t] * __fdividef(1.0f, fmaxf(d_gcnt[g], 1.0f));
    __syncthreads();
    float acc = b_l1[t];
#pragma unroll
    for (int f = 0; f < 64; f++)
        acc = fmaf(gsm[f], w_l1[f * HOUT + t], acc);
    float sp = lg2f(1.0f + ex2f(acc * L2E)) * LN2;
    red[t] = sp * w_out[t];
    __syncthreads();
    if (t < 64) red[t] += red[t + 64];
    __syncthreads();
    if (t < 32) {
        float s = red[t] + red[t + 32];
#pragma unroll
        for (int off = 16; off > 0; off >>= 1)
            s += __shfl_down_sync(0xffffffff, s, off);
        if (t == 0) out[g] = s + b_out[0];
    }
}

// ---------------- launch ----------------
extern "C" void kernel_launch(void* const* d_in, const int* in_sizes, int n_in,
                              void* d_out_p, int out_size) {
    const int*   atom_z = (const int*)d_in[0];
    const float* attr   = (const float*)d_in[1];
    const int*   hei    = (const int*)d_in[2];
    const int*   batch  = (const int*)d_in[3];
    const float* emb    = (const float*)d_in[4];
    const float* w_f    = (const float*)d_in[5];
    const float* b_f    = (const float*)d_in[6];
    const float* w_c    = (const float*)d_in[7];
    const float* b_c    = (const float*)d_in[8];
    const float* gamma  = (const float*)d_in[9];
    const float* beta   = (const float*)d_in[10];
    const float* w_l1   = (const float*)d_in[11];
    const float* b_l1   = (const float*)d_in[12];
    const float* w_out  = (const float*)d_in[13];
    const float* b_out  = (const float*)d_in[14];
    float* out = (float*)d_out_p;

    const int* src = hei;
    const int* hid = hei + NI;

    const int gemm_smem = (ZKP * 128 + 64 * ZKP) * (int)sizeof(float);  // 122880 B
    cudaFuncSetAttribute(k_gemm_motifs, cudaFuncAttributeMaxDynamicSharedMemorySize, gemm_smem);

    k_zero<<<512, 256>>>();
    k_tables<<<NZ, 128>>>(emb, w_f, w_c);
    k_counts<<<(NI + 255) / 256, 256>>>(src, hid, batch);
    k_scan1<<<dim3(SCAN_BLOCKS, 2), 256>>>();
    k_scan2<<<2, 256>>>();
    k_scan3<<<dim3(SCAN_BLOCKS, 2), 256>>>();
    k_sort<<<(NI + 255) / 256, 256>>>(src, hid, atom_z);
    k_hx<<<(NM + 15) / 16, 256>>>(emb);
    k_gemm_motifs<<<(NM + 63) / 64, 256, gemm_smem>>>(w_f, w_c, b_f, b_c, attr);
    k_msg<<<(NGRP + 15) / 16, 256>>>(atom_z);
    k_bnstats<<<256, 256>>>();
    k_final<<<(NA * 16 + 255) / 256, 256>>>(batch, gamma, beta, atom_z, emb);
    k_head<<<NG, 128>>>(w_l1, b_l1, w_out, b_out, out);
}

// round 6
// speedup vs baseline: 2.5018x; 1.6131x over previous
#include <cuda_runtime.h>

#define NA 50000
#define NM 50000
#define NI 600000
#define NG 512
#define H 64
#define MD 94
#define HOUT 128
#define KA 96             // attr K padded (94 -> 96)
#define NZ 101
#define BN_EPS 1e-5f
#define SCAN_BLOCKS 196   // ceil(50000/256)
#define NGRP (NI / 16)    // 37500

// ---------------- device scratch ----------------
__device__ __align__(256) float d_Tf[NZ * H];
__device__ __align__(256) float d_Tc[NZ * H];
__device__ __align__(256) float d_U[NZ * 128];    // emb @ W[64:128] (f|c halves)
__device__ __align__(256) float d_hxw[NM * 128];  // sum over motif of U[z]
__device__ __align__(256) float d_Mf[NM * H];
__device__ __align__(256) float d_Mc[NM * H];
__device__ __align__(256) float d_osum[NA * H];
__device__ float d_bnsum[H];
__device__ float d_bnsq[H];
__device__ __align__(256) float d_gsum[NG * H];
__device__ float d_gcnt[NG];
// sort machinery (both sides)
__device__ int d_icnt_s[NA];
__device__ int d_icnt_h[NM];
__device__ int d_off_s[NA + 1];
__device__ int d_off_h[NM + 1];
__device__ int d_cur_s[NA];
__device__ int d_cur_h[NM];
__device__ int d_bsum[2][SCAN_BLOCKS];
__device__ int d_boff[2][SCAN_BLOCKS];
__device__ float d_rcs[NA];
__device__ float d_rch[NM];
__device__ int   d_zA[NI];        // atom TYPE per incidence, sorted by hid
__device__ uint2 d_hsB[NI];       // {motif, atom} per incidence, sorted by src

// ---------------- fast math ----------------
__device__ __forceinline__ float ex2f(float x) { float r; asm("ex2.approx.ftz.f32 %0,%1;" : "=f"(r) : "f"(x)); return r; }
__device__ __forceinline__ float lg2f(float x) { float r; asm("lg2.approx.ftz.f32 %0,%1;" : "=f"(r) : "f"(x)); return r; }
__device__ __forceinline__ float rcpf(float x) { float r; asm("rcp.approx.ftz.f32 %0,%1;" : "=f"(r) : "f"(x)); return r; }

#define L2E 1.4426950408889634f
#define LN2 0.6931471805599453f

__device__ __forceinline__ float gatef(float a, float b) {
    float sg = rcpf(1.0f + ex2f(-a * L2E));
    float sp = lg2f(1.0f + ex2f(b * L2E)) * LN2;
    return sg * sp;
}

__device__ __forceinline__ void red_add_v4(float* p, float4 v) {
    asm volatile("red.global.add.v4.f32 [%0], {%1,%2,%3,%4};"
                 :: "l"(p), "f"(v.x), "f"(v.y), "f"(v.z), "f"(v.w) : "memory");
}
__device__ __forceinline__ void red_add_1(float* p, float v) {
    asm volatile("red.global.add.f32 [%0], %1;" :: "l"(p), "f"(v) : "memory");
}

// ---------------- kernels ----------------
__global__ void k_zero() {
    int tid = blockIdx.x * blockDim.x + threadIdx.x;
    int stride = gridDim.x * blockDim.x;
    for (int i = tid; i < NA * H; i += stride) d_osum[i] = 0.f;
    for (int i = tid; i < NA; i += stride) d_icnt_s[i] = 0;
    for (int i = tid; i < NM; i += stride) d_icnt_h[i] = 0;
    for (int i = tid; i < NG * H; i += stride) d_gsum[i] = 0.f;
    if (tid < NG) d_gcnt[tid] = 0.f;
    if (tid < H) { d_bnsum[tid] = 0.f; d_bnsq[tid] = 0.f; }
    if (tid == 0) { d_off_s[NA] = NI; d_off_h[NM] = NI; }
}

// tables: Tf/Tc = emb@W[:64] halves; U = emb@W[64:128] halves (101 x 128)
__global__ __launch_bounds__(256) void k_tables(const float* __restrict__ emb,
                                                const float* __restrict__ w_f,
                                                const float* __restrict__ w_c) {
    __shared__ float e[H];
    int z = blockIdx.x;
    int t = threadIdx.x;
    if (t < H) e[t] = emb[z * H + t];
    __syncthreads();
    float acc = 0.f;
    if (t < 64) {
#pragma unroll 8
        for (int k = 0; k < H; k++) acc = fmaf(e[k], w_f[k * H + t], acc);
        d_Tf[z * H + t] = acc;
    } else if (t < 128) {
        int j = t - 64;
#pragma unroll 8
        for (int k = 0; k < H; k++) acc = fmaf(e[k], w_c[k * H + j], acc);
        d_Tc[z * H + j] = acc;
    } else if (t < 192) {
        int j = t - 128;
#pragma unroll 8
        for (int k = 0; k < H; k++) acc = fmaf(e[k], w_f[(64 + k) * H + j], acc);
        d_U[z * 128 + j] = acc;
    } else {
        int j = t - 192;
#pragma unroll 8
        for (int k = 0; k < H; k++) acc = fmaf(e[k], w_c[(64 + k) * H + j], acc);
        d_U[z * 128 + 64 + j] = acc;
    }
}

__global__ void k_counts(const int* __restrict__ src, const int* __restrict__ hid,
                         const int* __restrict__ batch) {
    int e = blockIdx.x * blockDim.x + threadIdx.x;
    if (e < NI) {
        atomicAdd(&d_icnt_s[src[e]], 1);
        atomicAdd(&d_icnt_h[hid[e]], 1);
    }
    if (e < NA) red_add_1(&d_gcnt[batch[e]], 1.0f);
}

// ---- exclusive scan over both count arrays ----
__global__ __launch_bounds__(256) void k_scan1() {
    __shared__ int sh[256];
    int side = blockIdx.y;
    const int* cnt = side ? d_icnt_h : d_icnt_s;
    int* off = side ? d_off_h : d_off_s;
    int t = threadIdx.x;
    int i = blockIdx.x * 256 + t;
    int v = (i < NA) ? cnt[i] : 0;
    sh[t] = v;
    __syncthreads();
#pragma unroll
    for (int d = 1; d < 256; d <<= 1) {
        int u = (t >= d) ? sh[t - d] : 0;
        __syncthreads();
        sh[t] += u;
        __syncthreads();
    }
    if (i < NA) off[i] = sh[t] - v;
    if (t == 255) d_bsum[side][blockIdx.x] = sh[255];
}

__global__ __launch_bounds__(256) void k_scan2() {
    __shared__ int sh[256];
    int side = blockIdx.x;
    int t = threadIdx.x;
    int v = (t < SCAN_BLOCKS) ? d_bsum[side][t] : 0;
    sh[t] = v;
    __syncthreads();
#pragma unroll
    for (int d = 1; d < 256; d <<= 1) {
        int u = (t >= d) ? sh[t - d] : 0;
        __syncthreads();
        sh[t] += u;
        __syncthreads();
    }
    if (t < SCAN_BLOCKS) d_boff[side][t] = sh[t] - v;
}

__global__ __launch_bounds__(256) void k_scan3() {
    int side = blockIdx.y;
    int i = blockIdx.x * 256 + threadIdx.x;
    if (i >= NA) return;
    if (side == 0) {
        int o = d_off_s[i] + d_boff[0][blockIdx.x];
        d_off_s[i] = o;
        d_cur_s[i] = o;
        d_rcs[i] = __fdividef(1.0f, fmaxf((float)d_icnt_s[i], 1.0f));
    } else {
        int o = d_off_h[i] + d_boff[1][blockIdx.x];
        d_off_h[i] = o;
        d_cur_h[i] = o;
        d_rch[i] = __fdividef(1.0f, fmaxf((float)d_icnt_h[i], 1.0f));
    }
}

__global__ void k_sort(const int* __restrict__ src, const int* __restrict__ hid,
                       const int* __restrict__ az) {
    int e = blockIdx.x * blockDim.x + threadIdx.x;
    if (e >= NI) return;
    int s = src[e];
    int h = hid[e];
    int z = __ldg(az + s);
    int ph = atomicAdd(&d_cur_h[h], 1);
    d_zA[ph] = z;
    int ps = atomicAdd(&d_cur_s[s], 1);
    d_hsB[ps] = make_uint2((unsigned)h, (unsigned)s);
}

// phase A: hxw[m][0:128] = sum over segment of U[z]  (32 threads / motif)
__global__ __launch_bounds__(256) void k_hxw() {
    int m = blockIdx.x * 8 + (threadIdx.x >> 5);
    if (m >= NM) return;
    int q = (threadIdx.x & 31) << 2;
    int b = d_off_h[m], e = d_off_h[m + 1];
    float4 acc = make_float4(0.f, 0.f, 0.f, 0.f);
    int j = b;
    for (; j + 3 < e; j += 4) {
        int z0 = __ldg(d_zA + j), z1 = __ldg(d_zA + j + 1);
        int z2 = __ldg(d_zA + j + 2), z3 = __ldg(d_zA + j + 3);
        float4 v0 = __ldg((const float4*)(d_U + z0 * 128 + q));
        float4 v1 = __ldg((const float4*)(d_U + z1 * 128 + q));
        float4 v2 = __ldg((const float4*)(d_U + z2 * 128 + q));
        float4 v3 = __ldg((const float4*)(d_U + z3 * 128 + q));
        acc.x += (v0.x + v1.x) + (v2.x + v3.x);
        acc.y += (v0.y + v1.y) + (v2.y + v3.y);
        acc.z += (v0.z + v1.z) + (v2.z + v3.z);
        acc.w += (v0.w + v1.w) + (v2.w + v3.w);
    }
    for (; j < e; j++) {
        int z = __ldg(d_zA + j);
        float4 v = __ldg((const float4*)(d_U + z * 128 + q));
        acc.x += v.x; acc.y += v.y; acc.z += v.z; acc.w += v.w;
    }
    *reinterpret_cast<float4*>(&d_hxw[m * 128 + q]) = acc;
}

// motif GEMM (attr only, K=96): [Mf|Mc] = attr @ W[128:222] + hxw*rch + bias
__global__ __launch_bounds__(256) void k_gemm_motifs(const float* __restrict__ w_f,
                                                     const float* __restrict__ w_c,
                                                     const float* __restrict__ b_f,
                                                     const float* __restrict__ b_c,
                                                     const float* __restrict__ attr) {
    __shared__ float Wsm[KA * 128];   // 48 KB
    __shared__ float Xsm[64 * KA];    // 24 KB
    int t = threadIdx.x;
    int tx = t & 31;
    int ry = t >> 5;

    for (int idx = t; idx < KA * 128; idx += 256) {
        int k = idx >> 7, j = idx & 127;
        float v = 0.f;
        if (k < MD) v = (j < 64) ? w_f[(128 + k) * H + j] : w_c[(128 + k) * H + j - 64];
        Wsm[idx] = v;
    }
    int row0 = blockIdx.x * 64;
    for (int idx = t; idx < 64 * KA; idx += 256) {
        int r = idx / KA;
        int k = idx - r * KA;
        int row = row0 + r;
        float v = 0.f;
        if (row < NM && k < MD) v = attr[row * MD + k];
        Xsm[idx] = v;
    }
    __syncthreads();

    float acc[8][4];
#pragma unroll
    for (int r = 0; r < 8; r++)
#pragma unroll
        for (int c = 0; c < 4; c++) acc[r][c] = 0.f;

    for (int k0 = 0; k0 < KA; k0 += 4) {
        float4 wv[4];
#pragma unroll
        for (int i = 0; i < 4; i++)
            wv[i] = *reinterpret_cast<const float4*>(&Wsm[(k0 + i) * 128 + tx * 4]);
#pragma unroll
        for (int r = 0; r < 8; r++) {
            float4 xv = *reinterpret_cast<const float4*>(&Xsm[(ry * 8 + r) * KA + k0]);
            acc[r][0] = fmaf(xv.x, wv[0].x, acc[r][0]);
            acc[r][1] = fmaf(xv.x, wv[0].y, acc[r][1]);
            acc[r][2] = fmaf(xv.x, wv[0].z, acc[r][2]);
            acc[r][3] = fmaf(xv.x, wv[0].w, acc[r][3]);
            acc[r][0] = fmaf(xv.y, wv[1].x, acc[r][0]);
            acc[r][1] = fmaf(xv.y, wv[1].y, acc[r][1]);
            acc[r][2] = fmaf(xv.y, wv[1].z, acc[r][2]);
            acc[r][3] = fmaf(xv.y, wv[1].w, acc[r][3]);
            acc[r][0] = fmaf(xv.z, wv[2].x, acc[r][0]);
            acc[r][1] = fmaf(xv.z, wv[2].y, acc[r][1]);
            acc[r][2] = fmaf(xv.z, wv[2].z, acc[r][2]);
            acc[r][3] = fmaf(xv.z, wv[2].w, acc[r][3]);
            acc[r][0] = fmaf(xv.w, wv[3].x, acc[r][0]);
            acc[r][1] = fmaf(xv.w, wv[3].y, acc[r][1]);
            acc[r][2] = fmaf(xv.w, wv[3].z, acc[r][2]);
            acc[r][3] = fmaf(xv.w, wv[3].w, acc[r][3]);
        }
    }

    int col = tx * 4;
    float4 bias;
    if (col < 64) bias = *reinterpret_cast<const float4*>(&b_f[col]);
    else          bias = *reinterpret_cast<const float4*>(&b_c[col - 64]);
#pragma unroll
    for (int r = 0; r < 8; r++) {
        int row = row0 + ry * 8 + r;
        if (row < NM) {
            float rc = d_rch[row];
            float4 hw = *reinterpret_cast<const float4*>(&d_hxw[row * 128 + col]);
            float4 o;
            o.x = acc[r][0] + hw.x * rc + bias.x;
            o.y = acc[r][1] + hw.y * rc + bias.y;
            o.z = acc[r][2] + hw.z * rc + bias.z;
            o.w = acc[r][3] + hw.w * rc + bias.w;
            if (col < 64) *reinterpret_cast<float4*>(&d_Mf[row * H + col]) = o;
            else          *reinterpret_cast<float4*>(&d_Mc[row * H + col - 64]) = o;
        }
    }
}

// phase B: src-sorted chunks; register run-accumulation, red.v4 flush on atom change
__global__ __launch_bounds__(256) void k_msg(const int* __restrict__ az) {
    int t = threadIdx.x;
    int grp = blockIdx.x * 16 + (t >> 4);
    if (grp >= NGRP) return;
    int q = (t & 15) << 2;
    int B = grp * 16;

    int cur = -1;
    float4 acc = make_float4(0.f, 0.f, 0.f, 0.f);
    float4 tf = acc, tc = acc;

#pragma unroll
    for (int i0 = 0; i0 < 16; i0 += 4) {
        uint2 hs[4];
#pragma unroll
        for (int j = 0; j < 4; j++) hs[j] = __ldg(&d_hsB[B + i0 + j]);
        float4 mf[4], mc[4];
#pragma unroll
        for (int j = 0; j < 4; j++) {
            int m = (int)hs[j].x;
            mf[j] = __ldg((const float4*)(d_Mf + m * H + q));
            mc[j] = __ldg((const float4*)(d_Mc + m * H + q));
        }
#pragma unroll
        for (int j = 0; j < 4; j++) {
            int s = (int)hs[j].y;
            if (s != cur) {
                if (cur >= 0) red_add_v4(&d_osum[cur * H + q], acc);
                cur = s;
                acc = make_float4(0.f, 0.f, 0.f, 0.f);
                int z = __ldg(az + s);
                tf = __ldg((const float4*)(d_Tf + z * H + q));
                tc = __ldg((const float4*)(d_Tc + z * H + q));
            }
            acc.x += gatef(tf.x + mf[j].x, tc.x + mc[j].x);
            acc.y += gatef(tf.y + mf[j].y, tc.y + mc[j].y);
            acc.z += gatef(tf.z + mf[j].z, tc.z + mc[j].z);
            acc.w += gatef(tf.w + mf[j].w, tc.w + mc[j].w);
        }
    }
    red_add_v4(&d_osum[cur * H + q], acc);
}

// BN statistics over out = osum * rcs
__global__ __launch_bounds__(256) void k_bnstats() {
    __shared__ float b1[64], b2[64];
    int t = threadIdx.x;
    if (t < 64) { b1[t] = 0.f; b2[t] = 0.f; }
    __syncthreads();
    int start = blockIdx.x * 256 + t;
    int q = (start & 15) << 2;
    float l1[4] = {0.f, 0.f, 0.f, 0.f};
    float l2[4] = {0.f, 0.f, 0.f, 0.f};
    for (int idx = start; idx < NA * 16; idx += 65536) {
        int i = idx >> 4;
        float rc = d_rcs[i];
        float4 o = *reinterpret_cast<const float4*>(&d_osum[i * H + q]);
        o.x *= rc; o.y *= rc; o.z *= rc; o.w *= rc;
        l1[0] += o.x; l2[0] += o.x * o.x;
        l1[1] += o.y; l2[1] += o.y * o.y;
        l1[2] += o.z; l2[2] += o.z * o.z;
        l1[3] += o.w; l2[3] += o.w * o.w;
    }
#pragma unroll
    for (int c = 0; c < 4; c++) {
        atomicAdd(&b1[q + c], l1[c]);
        atomicAdd(&b2[q + c], l2[c]);
    }
    __syncthreads();
    if (t < 64) {
        red_add_1(&d_bnsum[t], b1[t]);
        red_add_1(&d_bnsq[t], b2[t]);
    }
}

// normalize + residual + relu + pool
__global__ void k_final(const int* __restrict__ batch, const float* __restrict__ gamma,
                        const float* __restrict__ beta, const int* __restrict__ az,
                        const float* __restrict__ emb) {
    int tid = blockIdx.x * blockDim.x + threadIdx.x;
    if (tid >= NA * 16) return;
    int i = tid >> 4;
    int q = (tid & 15) << 2;
    int z = __ldg(az + i);
    float rc = d_rcs[i];
    float4 o = *reinterpret_cast<const float4*>(&d_osum[i * H + q]);
    float4 xv = __ldg((const float4*)(emb + z * H + q));
    float ov[4] = {o.x * rc, o.y * rc, o.z * rc, o.w * rc};
    float xr[4] = {xv.x, xv.y, xv.z, xv.w};
    float res[4];
#pragma unroll
    for (int c = 0; c < 4; c++) {
        int f = q + c;
        float mu = d_bnsum[f] * (1.0f / NA);
        float var = d_bnsq[f] * (1.0f / NA) - mu * mu;
        float inv = rsqrtf(var + BN_EPS);
        float v = (ov[c] - mu) * inv * gamma[f] + beta[f] + xr[c];
        res[c] = fmaxf(v, 0.f);
    }
    float4 r; r.x = res[0]; r.y = res[1]; r.z = res[2]; r.w = res[3];
    int g = __ldg(batch + i);
    red_add_v4(&d_gsum[g * H + q], r);
}

// MLP head
__global__ __launch_bounds__(128) void k_head(const float* __restrict__ w_l1,
                                              const float* __restrict__ b_l1,
                                              const float* __restrict__ w_out,
                                              const float* __restrict__ b_out,
                                              float* __restrict__ out) {
    __shared__ float gsm[64];
    __shared__ float red[128];
    int g = blockIdx.x;
    int t = threadIdx.x;
    if (t < 64) gsm[t] = d_gsum[g * H + t] * __fdividef(1.0f, fmaxf(d_gcnt[g], 1.0f));
    __syncthreads();
    float acc = b_l1[t];
#pragma unroll
    for (int f = 0; f < 64; f++)
        acc = fmaf(gsm[f], w_l1[f * HOUT + t], acc);
    float sp = lg2f(1.0f + ex2f(acc * L2E)) * LN2;
    red[t] = sp * w_out[t];
    __syncthreads();
    if (t < 64) red[t] += red[t + 64];
    __syncthreads();
    if (t < 32) {
        float s = red[t] + red[t + 32];
#pragma unroll
        for (int off = 16; off > 0; off >>= 1)
            s += __shfl_down_sync(0xffffffff, s, off);
        if (t == 0) out[g] = s + b_out[0];
    }
}

// ---------------- launch ----------------
extern "C" void kernel_launch(void* const* d_in, const int* in_sizes, int n_in,
                              void* d_out_p, int out_size) {
    const int*   atom_z = (const int*)d_in[0];
    const float* attr   = (const float*)d_in[1];
    const int*   hei    = (const int*)d_in[2];
    const int*   batch  = (const int*)d_in[3];
    const float* emb    = (const float*)d_in[4];
    const float* w_f    = (const float*)d_in[5];
    const float* b_f    = (const float*)d_in[6];
    const float* w_c    = (const float*)d_in[7];
    const float* b_c    = (const float*)d_in[8];
    const float* gamma  = (const float*)d_in[9];
    const float* beta   = (const float*)d_in[10];
    const float* w_l1   = (const float*)d_in[11];
    const float* b_l1   = (const float*)d_in[12];
    const float* w_out  = (const float*)d_in[13];
    const float* b_out  = (const float*)d_in[14];
    float* out = (float*)d_out_p;

    const int* src = hei;
    const int* hid = hei + NI;

    k_zero<<<512, 256>>>();
    k_tables<<<NZ, 256>>>(emb, w_f, w_c);
    k_counts<<<(NI + 255) / 256, 256>>>(src, hid, batch);
    k_scan1<<<dim3(SCAN_BLOCKS, 2), 256>>>();
    k_scan2<<<2, 256>>>();
    k_scan3<<<dim3(SCAN_BLOCKS, 2), 256>>>();
    k_sort<<<(NI + 255) / 256, 256>>>(src, hid, atom_z);
    k_hxw<<<(NM + 7) / 8, 256>>>();
    k_gemm_motifs<<<(NM + 63) / 64, 256>>>(w_f, w_c, b_f, b_c, attr);
    k_msg<<<(NGRP + 15) / 16, 256>>>(atom_z);
    k_bnstats<<<256, 256>>>();
    k_final<<<(NA * 16 + 255) / 256, 256>>>(batch, gamma, beta, atom_z, emb);
    k_head<<<NG, 128>>>(w_l1, b_l1, w_out, b_out, out);
}